// round 2
// baseline (speedup 1.0000x reference)
#include <cuda_runtime.h>
#include <cuda_bf16.h>
#include <math.h>

#define NG 20000
#define NP 100000
#define NM 5000
#define NTOT (NG + NP + NM)
#define HID 64
#define NLAYERS 2

// ---------------- scratch (static device globals; no allocs) ----------------
// h / hn packed: [gene | patient | group]
__device__ float g_h [NTOT * HID];
__device__ float g_hn[NTOT * HID];
__device__ float g_agg[NP * HID];          // reused per edge type (max dst = NP)
__device__ float g_deg[4][NP];             // per-edge-type in-degree (float)

#define OFF_GENE 0
#define OFF_PAT  (NG * HID)
#define OFF_GRP  ((NG + NP) * HID)

// ---------------- small helpers ----------------
__device__ __forceinline__ float elu1(float x) { return x > 0.f ? x : expm1f(x); }

// grid-stride float4 zero (n must be multiple of 4 — all our sizes are)
__global__ void zero4_kernel(float4* p, int n4) {
    int i = blockIdx.x * blockDim.x + threadIdx.x;
    int stride = gridDim.x * blockDim.x;
    float4 z = make_float4(0.f, 0.f, 0.f, 0.f);
    for (; i < n4; i += stride) p[i] = z;
}

// encoder: h[n,j] = elu(b[j] + sum_k x[n,k] * W[k,j]),  K small
template <int K>
__global__ void encoder_kernel(const float* __restrict__ x,
                               const float* __restrict__ W,
                               const float* __restrict__ b,
                               float* __restrict__ h, int N) {
    int idx = blockIdx.x * blockDim.x + threadIdx.x;
    if (idx >= N * HID) return;
    int n = idx >> 6;
    int j = idx & 63;
    float acc = b[j];
#pragma unroll
    for (int k = 0; k < K; k++)
        acc += x[n * K + k] * W[k * HID + j];
    h[idx] = elu1(acc);
}

// degree count
__global__ void deg_kernel(const int* __restrict__ dst, int E, float* __restrict__ deg) {
    int i = blockIdx.x * blockDim.x + threadIdx.x;
    if (i < E) atomicAdd(&deg[dst[i]], 1.0f);
}

// scatter-add: agg[dst[e], :] += h_src[src[e], :]
// 16 lanes per edge, one float4 per lane, red.global.add.v4.f32 (no return).
__global__ void scatter_kernel(const float* __restrict__ h_src,
                               const int* __restrict__ src,
                               const int* __restrict__ dst,
                               int E, float* __restrict__ agg) {
    int gtid = blockIdx.x * blockDim.x + threadIdx.x;
    int warp = gtid >> 5;
    int lane = threadIdx.x & 31;
    int e = warp * 2 + (lane >> 4);
    if (e >= E) return;
    int q = lane & 15;
    int s = src[e];
    int d = dst[e];
    const float4* sp = reinterpret_cast<const float4*>(h_src + (size_t)s * HID);
    float4 v = sp[q];
    float* dp = agg + (size_t)d * HID + q * 4;
    asm volatile("red.global.add.v4.f32 [%0], {%1,%2,%3,%4};"
                 :: "l"(dp), "f"(v.x), "f"(v.y), "f"(v.z), "f"(v.w)
                 : "memory");
}

// SAGE linear: hn[n,:] += (agg[n,:]/max(deg,1)) @ Wl + bl + h_root[n,:] @ Wr
// weights in shared; 4 nodes per 256-thread block.
__global__ void sage_linear_kernel(const float* __restrict__ agg,
                                   const float* __restrict__ deg,
                                   const float* __restrict__ h_root,
                                   const float* __restrict__ Wl,
                                   const float* __restrict__ bl,
                                   const float* __restrict__ Wr,
                                   float* __restrict__ hn, int N) {
    __shared__ float sWl[HID * HID];
    __shared__ float sWr[HID * HID];
    __shared__ float sb[HID];
    __shared__ float sA[4][HID];
    __shared__ float sR[4][HID];
    for (int i = threadIdx.x; i < HID * HID; i += blockDim.x) {
        sWl[i] = Wl[i];
        sWr[i] = Wr[i];
    }
    if (threadIdx.x < HID) sb[threadIdx.x] = bl[threadIdx.x];
    __syncthreads();

    int g = threadIdx.x >> 6;   // node slot 0..3
    int j = threadIdx.x & 63;   // output column
    int n = blockIdx.x * 4 + g;

    if (n < N) {
        float dv = deg[n];
        dv = dv > 1.f ? dv : 1.f;
        sA[g][j] = agg[(size_t)n * HID + j] * (1.f / dv);
        sR[g][j] = h_root[(size_t)n * HID + j];
    }
    __syncthreads();
    if (n < N) {
        float acc = sb[j];
#pragma unroll
        for (int k = 0; k < HID; k++)
            acc += sA[g][k] * sWl[k * HID + j] + sR[g][k] * sWr[k * HID + j];
        hn[(size_t)n * HID + j] += acc;
    }
}

// residual + layernorm + elu, in place on h. One warp per node, 2 elems/lane.
__global__ void update_kernel(float* __restrict__ h,
                              const float* __restrict__ hn,
                              const float* __restrict__ gamma,
                              const float* __restrict__ beta, int N) {
    int warp = (blockIdx.x * blockDim.x + threadIdx.x) >> 5;
    int lane = threadIdx.x & 31;
    if (warp >= N) return;
    size_t base = (size_t)warp * HID;
    float a = h[base + lane]       + hn[base + lane];
    float c = h[base + 32 + lane]  + hn[base + 32 + lane];
    float s = a + c;
#pragma unroll
    for (int o = 16; o; o >>= 1) s += __shfl_xor_sync(0xFFFFFFFFu, s, o);
    float mean = s * (1.f / 64.f);
    float da = a - mean, dc = c - mean;
    float vs = da * da + dc * dc;
#pragma unroll
    for (int o = 16; o; o >>= 1) vs += __shfl_xor_sync(0xFFFFFFFFu, vs, o);
    float rstd = rsqrtf(vs * (1.f / 64.f) + 1e-5f);
    float y1 = da * rstd * gamma[lane]      + beta[lane];
    float y2 = dc * rstd * gamma[32 + lane] + beta[32 + lane];
    h[base + lane]      = elu1(y1);
    h[base + 32 + lane] = elu1(y2);
}

// cox head: one warp per patient.
__global__ void cox_kernel(const float* __restrict__ h,
                           const float* __restrict__ W1,
                           const float* __restrict__ b1,
                           const float* __restrict__ W2,
                           const float* __restrict__ b2,
                           float* __restrict__ out, int N) {
    __shared__ float sW1[HID * 32];
    __shared__ float sb1[32];
    __shared__ float sW2[32];
    __shared__ float sb2;
    for (int i = threadIdx.x; i < HID * 32; i += blockDim.x) sW1[i] = W1[i];
    if (threadIdx.x < 32) { sb1[threadIdx.x] = b1[threadIdx.x]; sW2[threadIdx.x] = W2[threadIdx.x]; }
    if (threadIdx.x == 0) sb2 = b2[0];
    __syncthreads();

    int warp = (blockIdx.x * blockDim.x + threadIdx.x) >> 5;
    int lane = threadIdx.x & 31;
    if (warp >= N) return;
    size_t base = (size_t)warp * HID;
    float a = h[base + lane];
    float c = h[base + 32 + lane];
    float z = sb1[lane];
#pragma unroll
    for (int k = 0; k < 32; k++) {
        float hk = __shfl_sync(0xFFFFFFFFu, a, k);
        z += hk * sW1[k * 32 + lane];
    }
#pragma unroll
    for (int k = 0; k < 32; k++) {
        float hk = __shfl_sync(0xFFFFFFFFu, c, k);
        z += hk * sW1[(k + 32) * 32 + lane];
    }
    z = elu1(z);
    float hz = z * sW2[lane];
#pragma unroll
    for (int o = 16; o; o >>= 1) hz += __shfl_xor_sync(0xFFFFFFFFu, hz, o);
    if (lane == 0) out[warp] = hz + sb2;
}

// ---------------- host launcher ----------------
static inline int cdiv(long long a, long long b) { return (int)((a + b - 1) / b); }

extern "C" void kernel_launch(void* const* d_in, const int* in_sizes, int n_in,
                              void* d_out, int out_size) {
    const float* x_gene = (const float*)d_in[0];
    const float* x_pat  = (const float*)d_in[1];
    const float* x_grp  = (const float*)d_in[2];
    const int* src[4] = { (const int*)d_in[3], (const int*)d_in[5],
                          (const int*)d_in[7], (const int*)d_in[9] };
    const int* dst[4] = { (const int*)d_in[4], (const int*)d_in[6],
                          (const int*)d_in[8], (const int*)d_in[10] };
    const float* encGW = (const float*)d_in[11];
    const float* encGb = (const float*)d_in[12];
    const float* encPW = (const float*)d_in[13];
    const float* encPb = (const float*)d_in[14];
    const float* encMW = (const float*)d_in[15];
    const float* encMb = (const float*)d_in[16];
    const float* convWl = (const float*)d_in[17];   // [2,4,64,64]
    const float* convbl = (const float*)d_in[18];   // [2,4,64]
    const float* convWr = (const float*)d_in[19];   // [2,4,64,64]
    const float* lnG = (const float*)d_in[20];      // [2,3,64]
    const float* lnB = (const float*)d_in[21];
    const float* coxW1 = (const float*)d_in[22];
    const float* coxb1 = (const float*)d_in[23];
    const float* coxW2 = (const float*)d_in[24];
    const float* coxb2 = (const float*)d_in[25];
    float* out = (float*)d_out;

    const int E = in_sizes[3];

    float *hbuf, *hnbuf, *agg, *degbase;
    cudaGetSymbolAddress((void**)&hbuf,    g_h);
    cudaGetSymbolAddress((void**)&hnbuf,   g_hn);
    cudaGetSymbolAddress((void**)&agg,     g_agg);
    cudaGetSymbolAddress((void**)&degbase, g_deg);

    float* h_gene  = hbuf  + OFF_GENE;
    float* h_pat   = hbuf  + OFF_PAT;
    float* h_grp   = hbuf  + OFF_GRP;
    float* hn_gene = hnbuf + OFF_GENE;
    float* hn_pat  = hnbuf + OFF_PAT;
    float* hn_grp  = hnbuf + OFF_GRP;
    float* deg[4] = { degbase, degbase + NP, degbase + 2 * NP, degbase + 3 * NP };

    // edge-type metadata
    const float* eh_src[4] = { h_gene, h_pat, h_gene, h_grp };
    int    Ndst[4]   = { NP, NG, NM, NG };
    float* hroot[4]  = { h_pat, h_gene, h_grp, h_gene };
    float* hnew[4]   = { hn_pat, hn_gene, hn_grp, hn_gene };

    // ---- encoders ----
    encoder_kernel<11><<<cdiv((long long)NG * HID, 256), 256>>>(x_gene, encGW, encGb, h_gene, NG);
    encoder_kernel<3> <<<cdiv((long long)NP * HID, 256), 256>>>(x_pat,  encPW, encPb, h_pat,  NP);
    encoder_kernel<4> <<<cdiv((long long)NM * HID, 256), 256>>>(x_grp,  encMW, encMb, h_grp,  NM);

    // ---- degrees (topology fixed; same for both layers) ----
    zero4_kernel<<<256, 256>>>((float4*)degbase, 4 * NP / 4);
    for (int e = 0; e < 4; e++)
        deg_kernel<<<cdiv(E, 256), 256>>>(dst[e], E, deg[e]);

    // ---- layers ----
    for (int layer = 0; layer < NLAYERS; layer++) {
        zero4_kernel<<<1024, 256>>>((float4*)hnbuf, NTOT * HID / 4);

        for (int e = 0; e < 4; e++) {
            int N = Ndst[e];
            zero4_kernel<<<1024, 256>>>((float4*)agg, N * HID / 4);
            // 16 lanes per edge => E*16 threads
            scatter_kernel<<<cdiv((long long)E * 16, 256), 256>>>(eh_src[e], src[e], dst[e], E, agg);
            const float* Wl = convWl + ((size_t)layer * 4 + e) * HID * HID;
            const float* bl = convbl + ((size_t)layer * 4 + e) * HID;
            const float* Wr = convWr + ((size_t)layer * 4 + e) * HID * HID;
            sage_linear_kernel<<<cdiv(N, 4), 256>>>(agg, deg[e], hroot[e], Wl, bl, Wr, hnew[e], N);
        }

        // node order: gene, patient, mutation_group
        update_kernel<<<cdiv((long long)NG * 32, 256), 256>>>(h_gene, hn_gene,
            lnG + ((size_t)layer * 3 + 0) * HID, lnB + ((size_t)layer * 3 + 0) * HID, NG);
        update_kernel<<<cdiv((long long)NP * 32, 256), 256>>>(h_pat, hn_pat,
            lnG + ((size_t)layer * 3 + 1) * HID, lnB + ((size_t)layer * 3 + 1) * HID, NP);
        update_kernel<<<cdiv((long long)NM * 32, 256), 256>>>(h_grp, hn_grp,
            lnG + ((size_t)layer * 3 + 2) * HID, lnB + ((size_t)layer * 3 + 2) * HID, NM);
    }

    // ---- cox head ----
    cox_kernel<<<cdiv((long long)NP * 32, 256), 256>>>(h_pat, coxW1, coxb1, coxW2, coxb2, out, NP);
}

// round 6
// speedup vs baseline: 1.5445x; 1.5445x over previous
#include <cuda_runtime.h>
#include <cuda_bf16.h>
#include <math.h>

#define NG 20000
#define NP 100000
#define NM 5000
#define NTOT (NG + NP + NM)
#define HID 64
#define NLAYERS 2
#define EMAX 1000000
#define FULL 0xFFFFFFFFu

// ---------------- scratch (static device globals; no allocs) ----------------
__device__ float g_h [NTOT * HID];       // packed [gene | patient | group]
__device__ float g_hn[NTOT * HID];
__device__ float g_agg[NP * HID];        // reused per edge type (max dst = NP)
__device__ int   g_cnt[4][NP];           // per-type dst counts
__device__ int   g_off[4][NP + 1];       // CSR offsets
__device__ int   g_cur[4][NP + 1];       // fill cursors
__device__ int   g_col[4][EMAX];         // CSR column (src) indices

#define OFF_GENE 0
#define OFF_PAT  (NG * HID)
#define OFF_GRP  ((NG + NP) * HID)

__device__ __forceinline__ float elu1(float x) { return x > 0.f ? x : expm1f(x); }

// ---------------- utility kernels ----------------
__global__ void zero_int_kernel(int* p, int n) {
    int i = blockIdx.x * blockDim.x + threadIdx.x;
    int stride = gridDim.x * blockDim.x;
    for (; i < n; i += stride) p[i] = 0;
}

__global__ void copy_int_kernel(int* dst, const int* src, int n) {
    int i = blockIdx.x * blockDim.x + threadIdx.x;
    int stride = gridDim.x * blockDim.x;
    for (; i < n; i += stride) dst[i] = src[i];
}

// encoder: h[n,j] = elu(b[j] + sum_k x[n,k] * W[k,j])
template <int K>
__global__ void encoder_kernel(const float* __restrict__ x,
                               const float* __restrict__ W,
                               const float* __restrict__ b,
                               float* __restrict__ h, int N) {
    int idx = blockIdx.x * blockDim.x + threadIdx.x;
    if (idx >= N * HID) return;
    int n = idx >> 6;
    int j = idx & 63;
    float acc = b[j];
#pragma unroll
    for (int k = 0; k < K; k++)
        acc += x[n * K + k] * W[k * HID + j];
    h[idx] = elu1(acc);
}

// ---------------- CSR build ----------------
__global__ void count_kernel(const int* __restrict__ dst, int E, int* __restrict__ cnt) {
    int i = blockIdx.x * blockDim.x + threadIdx.x;
    if (i < E) atomicAdd(&cnt[dst[i]], 1);
}

// one block per edge type; exclusive scan of counts into offsets
__global__ void scan4_kernel(const int* __restrict__ cnt_base, int* __restrict__ off_base, int E) {
    const int Ns[4] = { NP, NG, NM, NG };
    int t = blockIdx.x;
    const int* cnt = cnt_base + t * NP;
    int* off = off_base + t * (NP + 1);
    int N = Ns[t];

    __shared__ int wsum[32];
    __shared__ int carry_s;
    if (threadIdx.x == 0) carry_s = 0;
    __syncthreads();
    int lane = threadIdx.x & 31, wid = threadIdx.x >> 5;
    int nw = blockDim.x >> 5;

    for (int base = 0; base < N; base += blockDim.x) {
        int i = base + threadIdx.x;
        int v = (i < N) ? cnt[i] : 0;
        int x = v;
#pragma unroll
        for (int o = 1; o < 32; o <<= 1) { int tt = __shfl_up_sync(FULL, x, o); if (lane >= o) x += tt; }
        if (lane == 31) wsum[wid] = x;
        __syncthreads();
        if (wid == 0) {
            int w = (lane < nw) ? wsum[lane] : 0;
#pragma unroll
            for (int o = 1; o < 32; o <<= 1) { int tt = __shfl_up_sync(FULL, w, o); if (lane >= o) w += tt; }
            wsum[lane] = w;
        }
        __syncthreads();
        int incl = x + (wid > 0 ? wsum[wid - 1] : 0);
        int carry = carry_s;
        if (i < N) off[i] = carry + incl - v;       // exclusive
        __syncthreads();
        if (threadIdx.x == blockDim.x - 1) carry_s = carry + incl;
        __syncthreads();
    }
    if (threadIdx.x == 0) off[N] = E;
}

__global__ void fill_kernel(const int* __restrict__ src, const int* __restrict__ dst,
                            int E, int* __restrict__ cur, int* __restrict__ col) {
    int i = blockIdx.x * blockDim.x + threadIdx.x;
    if (i < E) {
        int p = atomicAdd(&cur[dst[i]], 1);
        col[p] = src[i];
    }
}

// ---------------- pull aggregation (mean) ----------------
// one warp per dst node; lane holds elements [lane] and [32+lane] of the row
__global__ void pull_kernel(const float* __restrict__ h_src,
                            const int* __restrict__ off,
                            const int* __restrict__ col,
                            float* __restrict__ agg, int N) {
    int warp = (blockIdx.x * blockDim.x + threadIdx.x) >> 5;
    int lane = threadIdx.x & 31;
    if (warp >= N) return;
    int o0 = off[warp], o1 = off[warp + 1];
    float acc0 = 0.f, acc1 = 0.f;
    for (int base = o0; base < o1; base += 32) {
        int idx = (base + lane < o1) ? col[base + lane] : 0;
        int m = min(32, o1 - base);
#pragma unroll 4
        for (int j = 0; j < m; j++) {
            int s = __shfl_sync(FULL, idx, j);
            const float* r = h_src + (size_t)s * HID;
            acc0 += __ldg(r + lane);
            acc1 += __ldg(r + 32 + lane);
        }
    }
    float inv = 1.f / fmaxf((float)(o1 - o0), 1.f);
    agg[(size_t)warp * HID + lane]      = acc0 * inv;
    agg[(size_t)warp * HID + 32 + lane] = acc1 * inv;
}

// ---------------- SAGE linear: hn[n,:] (=|+=) agg@Wl + bl + h_root@Wr ----------------
// 64-node tiles, 4x4 register blocking, weights loaded once per (persistent) block.
// dynamic smem: sWl[4096] | sWr[4096] | sA[4096] | sR[4096]
__global__ void sage_linear_kernel(const float* __restrict__ agg,
                                   const float* __restrict__ h_root,
                                   const float* __restrict__ Wl,
                                   const float* __restrict__ bl,
                                   const float* __restrict__ Wr,
                                   float* __restrict__ hn, int N, int accum) {
    extern __shared__ float sm[];
    float* sWl = sm;
    float* sWr = sm + 4096;
    float* sA  = sm + 8192;
    float* sR  = sm + 12288;

    for (int i = threadIdx.x; i < 4096; i += 256) {
        sWl[i] = Wl[i];
        sWr[i] = Wr[i];
    }
    int tx = threadIdx.x & 15;   // col group: j0 = tx*4
    int ty = threadIdx.x >> 4;   // node group: nb = ty*4
    int j0 = tx * 4;
    int nb = ty * 4;
    float4 bias = *(const float4*)(bl + j0);
    __syncthreads();

    for (int n0 = blockIdx.x * 64; n0 < N; n0 += gridDim.x * 64) {
        // stage A and R tiles (float4 coalesced)
        for (int i = threadIdx.x; i < 64 * 16; i += 256) {
            int nn = i >> 4, q = i & 15;
            int n = n0 + nn;
            float4 va = make_float4(0.f, 0.f, 0.f, 0.f), vr = va;
            if (n < N) {
                va = ((const float4*)(agg    + (size_t)n * HID))[q];
                vr = ((const float4*)(h_root + (size_t)n * HID))[q];
            }
            *(float4*)&sA[nn * 64 + q * 4] = va;
            *(float4*)&sR[nn * 64 + q * 4] = vr;
        }
        __syncthreads();

        float acc[4][4];
#pragma unroll
        for (int i = 0; i < 4; i++) {
            acc[i][0] = bias.x; acc[i][1] = bias.y; acc[i][2] = bias.z; acc[i][3] = bias.w;
        }
#pragma unroll 8
        for (int k = 0; k < 64; k++) {
            float4 wl = *(const float4*)&sWl[k * 64 + j0];
            float4 wr = *(const float4*)&sWr[k * 64 + j0];
#pragma unroll
            for (int i = 0; i < 4; i++) {
                float a = sA[(nb + i) * 64 + k];
                float r = sR[(nb + i) * 64 + k];
                acc[i][0] += a * wl.x + r * wr.x;
                acc[i][1] += a * wl.y + r * wr.y;
                acc[i][2] += a * wl.z + r * wr.z;
                acc[i][3] += a * wl.w + r * wr.w;
            }
        }
#pragma unroll
        for (int i = 0; i < 4; i++) {
            int n = n0 + nb + i;
            if (n < N) {
                float* o = hn + (size_t)n * HID + j0;
                if (accum) {
                    o[0] += acc[i][0]; o[1] += acc[i][1];
                    o[2] += acc[i][2]; o[3] += acc[i][3];
                } else {
                    *(float4*)o = make_float4(acc[i][0], acc[i][1], acc[i][2], acc[i][3]);
                }
            }
        }
        __syncthreads();   // protect sA/sR before next tile overwrite
    }
}

// ---------------- residual + layernorm + elu over ALL node types ----------------
__global__ void update_all_kernel(float* __restrict__ h,
                                  const float* __restrict__ hn,
                                  const float* __restrict__ lnG,   // [3,64] for this layer
                                  const float* __restrict__ lnB) {
    int warp = (blockIdx.x * blockDim.x + threadIdx.x) >> 5;
    int lane = threadIdx.x & 31;
    if (warp >= NTOT) return;
    int t = (warp < NG) ? 0 : (warp < NG + NP ? 1 : 2);
    const float* gamma = lnG + t * HID;
    const float* beta  = lnB + t * HID;
    size_t base = (size_t)warp * HID;
    float a = h[base + lane]      + hn[base + lane];
    float c = h[base + 32 + lane] + hn[base + 32 + lane];
    float s = a + c;
#pragma unroll
    for (int o = 16; o; o >>= 1) s += __shfl_xor_sync(FULL, s, o);
    float mean = s * (1.f / 64.f);
    float da = a - mean, dc = c - mean;
    float vs = da * da + dc * dc;
#pragma unroll
    for (int o = 16; o; o >>= 1) vs += __shfl_xor_sync(FULL, vs, o);
    float rstd = rsqrtf(vs * (1.f / 64.f) + 1e-5f);
    h[base + lane]      = elu1(da * rstd * gamma[lane]      + beta[lane]);
    h[base + 32 + lane] = elu1(dc * rstd * gamma[32 + lane] + beta[32 + lane]);
}

// ---------------- cox head: one warp per patient ----------------
__global__ void cox_kernel(const float* __restrict__ h,
                           const float* __restrict__ W1,
                           const float* __restrict__ b1,
                           const float* __restrict__ W2,
                           const float* __restrict__ b2,
                           float* __restrict__ out, int N) {
    __shared__ float sW1[HID * 32];
    __shared__ float sb1[32];
    __shared__ float sW2[32];
    __shared__ float sb2;
    for (int i = threadIdx.x; i < HID * 32; i += blockDim.x) sW1[i] = W1[i];
    if (threadIdx.x < 32) { sb1[threadIdx.x] = b1[threadIdx.x]; sW2[threadIdx.x] = W2[threadIdx.x]; }
    if (threadIdx.x == 0) sb2 = b2[0];
    __syncthreads();

    int warp = (blockIdx.x * blockDim.x + threadIdx.x) >> 5;
    int lane = threadIdx.x & 31;
    if (warp >= N) return;
    size_t base = (size_t)warp * HID;
    float a = h[base + lane];
    float c = h[base + 32 + lane];
    float z = sb1[lane];
#pragma unroll
    for (int k = 0; k < 32; k++) {
        float hk = __shfl_sync(FULL, a, k);
        z += hk * sW1[k * 32 + lane];
    }
#pragma unroll
    for (int k = 0; k < 32; k++) {
        float hk = __shfl_sync(FULL, c, k);
        z += hk * sW1[(k + 32) * 32 + lane];
    }
    z = elu1(z);
    float hz = z * sW2[lane];
#pragma unroll
    for (int o = 16; o; o >>= 1) hz += __shfl_xor_sync(FULL, hz, o);
    if (lane == 0) out[warp] = hz + sb2;
}

// ---------------- host launcher ----------------
static inline int cdiv(long long a, long long b) { return (int)((a + b - 1) / b); }

extern "C" void kernel_launch(void* const* d_in, const int* in_sizes, int n_in,
                              void* d_out, int out_size) {
    const float* x_gene = (const float*)d_in[0];
    const float* x_pat  = (const float*)d_in[1];
    const float* x_grp  = (const float*)d_in[2];
    const int* src[4] = { (const int*)d_in[3], (const int*)d_in[5],
                          (const int*)d_in[7], (const int*)d_in[9] };
    const int* dst[4] = { (const int*)d_in[4], (const int*)d_in[6],
                          (const int*)d_in[8], (const int*)d_in[10] };
    const float* encGW = (const float*)d_in[11];
    const float* encGb = (const float*)d_in[12];
    const float* encPW = (const float*)d_in[13];
    const float* encPb = (const float*)d_in[14];
    const float* encMW = (const float*)d_in[15];
    const float* encMb = (const float*)d_in[16];
    const float* convWl = (const float*)d_in[17];   // [2,4,64,64]
    const float* convbl = (const float*)d_in[18];   // [2,4,64]
    const float* convWr = (const float*)d_in[19];   // [2,4,64,64]
    const float* lnG = (const float*)d_in[20];      // [2,3,64]
    const float* lnB = (const float*)d_in[21];
    const float* coxW1 = (const float*)d_in[22];
    const float* coxb1 = (const float*)d_in[23];
    const float* coxW2 = (const float*)d_in[24];
    const float* coxb2 = (const float*)d_in[25];
    float* out = (float*)d_out;

    const int E = in_sizes[3];

    float *hbuf, *hnbuf, *agg;
    int *cntb, *offb, *curb, *colb;
    cudaGetSymbolAddress((void**)&hbuf,  g_h);
    cudaGetSymbolAddress((void**)&hnbuf, g_hn);
    cudaGetSymbolAddress((void**)&agg,   g_agg);
    cudaGetSymbolAddress((void**)&cntb,  g_cnt);
    cudaGetSymbolAddress((void**)&offb,  g_off);
    cudaGetSymbolAddress((void**)&curb,  g_cur);
    cudaGetSymbolAddress((void**)&colb,  g_col);

    float* h_gene  = hbuf  + OFF_GENE;
    float* h_pat   = hbuf  + OFF_PAT;
    float* h_grp   = hbuf  + OFF_GRP;

    // per edge type: src features, dst count, root features, hn dst, accumulate?
    const float* eh_src[4] = { h_gene, h_pat, h_gene, h_grp };
    int    Ndst[4]   = { NP, NG, NM, NG };
    float* hroot[4]  = { h_pat, h_gene, h_grp, h_gene };
    float* hnew[4]   = { hnbuf + OFF_PAT, hnbuf + OFF_GENE, hnbuf + OFF_GRP, hnbuf + OFF_GENE };
    int    accum[4]  = { 0, 0, 0, 1 };   // gene hn written by e1, accumulated by e3

    static const int LIN_SMEM = 4 * 4096 * (int)sizeof(float);   // 64 KB
    cudaFuncSetAttribute(sage_linear_kernel,
                         cudaFuncAttributeMaxDynamicSharedMemorySize, LIN_SMEM);

    // ---- encoders ----
    encoder_kernel<11><<<cdiv((long long)NG * HID, 256), 256>>>(x_gene, encGW, encGb, h_gene, NG);
    encoder_kernel<3> <<<cdiv((long long)NP * HID, 256), 256>>>(x_pat,  encPW, encPb, h_pat,  NP);
    encoder_kernel<4> <<<cdiv((long long)NM * HID, 256), 256>>>(x_grp,  encMW, encMb, h_grp,  NM);

    // ---- CSR build (topology fixed; reused by both layers) ----
    zero_int_kernel<<<256, 256>>>(cntb, 4 * NP);
    for (int e = 0; e < 4; e++)
        count_kernel<<<cdiv(E, 256), 256>>>(dst[e], E, cntb + e * NP);
    scan4_kernel<<<4, 1024>>>(cntb, offb, E);
    copy_int_kernel<<<256, 256>>>(curb, offb, 4 * (NP + 1));
    for (int e = 0; e < 4; e++)
        fill_kernel<<<cdiv(E, 256), 256>>>(src[e], dst[e], E, curb + e * (NP + 1), colb + (size_t)e * EMAX);

    // ---- layers ----
    for (int layer = 0; layer < NLAYERS; layer++) {
        for (int e = 0; e < 4; e++) {
            int N = Ndst[e];
            pull_kernel<<<cdiv((long long)N * 32, 256), 256>>>(
                eh_src[e], offb + e * (NP + 1), colb + (size_t)e * EMAX, agg, N);
            const float* Wl = convWl + ((size_t)layer * 4 + e) * HID * HID;
            const float* bl = convbl + ((size_t)layer * 4 + e) * HID;
            const float* Wr = convWr + ((size_t)layer * 4 + e) * HID * HID;
            int grid = min(cdiv(N, 64), 592);
            sage_linear_kernel<<<grid, 256, LIN_SMEM>>>(agg, hroot[e], Wl, bl, Wr, hnew[e], N, accum[e]);
        }
        update_all_kernel<<<cdiv((long long)NTOT * 32, 256), 256>>>(
            hbuf, hnbuf, lnG + (size_t)layer * 3 * HID, lnB + (size_t)layer * 3 * HID);
    }

    // ---- cox head ----
    cox_kernel<<<cdiv((long long)NP * 32, 256), 256>>>(h_pat, coxW1, coxb1, coxW2, coxb2, out, NP);
}